// round 10
// baseline (speedup 1.0000x reference)
#include <cuda_runtime.h>
#include <cstdint>

#define NNODES 16383
#define EMBED 512
#define E4 128          // float4 per H row
#define NLEV 16
#define LEAVES 8192
#define MAXM 4096

#define AS_STR 264      // duplicated-A row stride (floats)
#define BS_STR 132      // B row stride (floats)
#define STAGE_F (16 * AS_STR + 16 * BS_STR)   // floats per stage = 6336
#define DYN_SMEM (2 * STAGE_F * 4)            // 50688 bytes

// ---------------- device scratch (static, no runtime alloc) ----------------
__device__ float4 g_H[NNODES * E4];          // 33.5 MB hidden states
__device__ float4 g_part[8 * MAXM * E4];     // 67 MB split-K partials
__device__ int    g_list[NLEV][MAXM];
__device__ int    g_cnt[NLEV];
__device__ unsigned g_arrive;
__device__ volatile unsigned g_release;

// ---------------- f32x2 helpers ----------------
__device__ __forceinline__ void fma2(unsigned long long& d,
                                     unsigned long long a, unsigned long long b) {
    asm("fma.rn.f32x2 %0, %1, %2, %0;" : "+l"(d) : "l"(a), "l"(b));
}
__device__ __forceinline__ unsigned long long pk2(float x, float y) {
    unsigned long long r;
    asm("mov.b64 %0, {%1, %2};" : "=l"(r) : "f"(x), "f"(y));
    return r;
}
__device__ __forceinline__ float2 upk2(unsigned long long v) {
    float2 r;
    asm("mov.b64 {%0, %1}, %2;" : "=f"(r.x), "=f"(r.y) : "l"(v));
    return r;
}

// ---------------- schedule kernels ----------------
__global__ void k_zero() {
    if (threadIdx.x < NLEV) g_cnt[threadIdx.x] = 0;
    if (threadIdx.x == 0) { g_arrive = 0; g_release = 0; }
}

__global__ void k_bucket(const int* __restrict__ is_leaf,
                         const int* __restrict__ left) {
    int i = blockIdx.x * blockDim.x + threadIdx.x;
    if (i >= NNODES) return;
    if (is_leaf[i]) return;
    int c = left[i];
    int d = 1;
    while (!is_leaf[c]) { c = left[c]; d++; if (d >= NLEV) break; }
    if (d >= NLEV) d = NLEV - 1;
    int slot = atomicAdd(&g_cnt[d], 1);
    if (slot < MAXM) g_list[d][slot] = i;
}

// ---------------- leaves: H[i] = relu(emb[word[i]]) ----------------
__global__ void k_leaf(const int* __restrict__ is_leaf,
                       const int* __restrict__ word,
                       const float4* __restrict__ emb4) {
    int t = blockIdx.x * blockDim.x + threadIdx.x;
    int node = t >> 7;
    if (node >= NNODES) return;
    if (!is_leaf[node]) return;
    int j = t & 127;
    float4 v = emb4[word[node] * E4 + j];
    v.x = fmaxf(v.x, 0.f); v.y = fmaxf(v.y, 0.f);
    v.z = fmaxf(v.z, 0.f); v.w = fmaxf(v.w, 0.f);
    g_H[node * E4 + j] = v;
}

// ---------------- split-K GEMM partial ----------------
// BM=128, BN=128, BK=16, 256 threads, 8x8 micro-tile, f32x2 FMAs.
// Double-buffered smem: one __syncthreads per BK chunk.
// A stored DUPLICATED ((v,v) pairs) so broadcast operands load pack-free.
__global__ __launch_bounds__(256, 2) void k_partial(
    int d, int ZS,
    const int* __restrict__ left, const int* __restrict__ right,
    const float4* __restrict__ W4)
{
    extern __shared__ float dsm[];
    __shared__ int s_src[128];

    int cnt = g_cnt[d];
    if (cnt == 0) return;
    const int* list = g_list[d];

    int z  = blockIdx.z;
    int n0 = blockIdx.y << 7;
    int kchunk4 = 256 / ZS;                       // float4s per K chunk
    int aoff4 = (z & ((ZS >> 1) - 1)) * kchunk4;
    int woff4 = z * kchunk4;
    bool useRight = (z >= (ZS >> 1));

    int tid = threadIdx.x;
    int tx = tid & 15, ty = tid >> 4;             // n = tx*8, m = ty*8
    int c4  = tid & 3;                            // k-f4 chunk within BK
    int row = tid >> 2;                           // 0..63
    int mtiles = (cnt + 127) >> 7;

    for (int bm = blockIdx.x; bm < mtiles; bm += gridDim.x) {
        if (tid < 128) {
            int m = bm * 128 + tid;
            int src = 0;
            if (m < cnt) {
                int node = list[m];
                src = useRight ? right[node] : left[node];
            }
            s_src[tid] = src;
        }
        __syncthreads();

        unsigned long long acc[8][4];
#pragma unroll
        for (int i = 0; i < 8; i++)
#pragma unroll
            for (int j = 0; j < 4; j++) acc[i][j] = 0ull;

        float4 va[2], vb[2];
#pragma unroll
        for (int r = 0; r < 2; r++) {
            int mr = row + r * 64;
            va[r] = g_H[s_src[mr] * E4 + aoff4 + c4];
            vb[r] = W4[(n0 + mr) * 256 + woff4 + c4];
        }
        // STS chunk 0 into stage 0 (A duplicated as (v,v) STS.64, B scalar)
        {
            float* As = dsm;
            float* Bs = dsm + 16 * AS_STR;
#pragma unroll
            for (int r = 0; r < 2; r++) {
                int mr = row + r * 64;
                float av[4] = {va[r].x, va[r].y, va[r].z, va[r].w};
                float bv[4] = {vb[r].x, vb[r].y, vb[r].z, vb[r].w};
#pragma unroll
                for (int q = 0; q < 4; q++) {
                    *(unsigned long long*)&As[(c4 * 4 + q) * AS_STR + 2 * mr] =
                        pk2(av[q], av[q]);
                    Bs[(c4 * 4 + q) * BS_STR + mr] = bv[q];
                }
            }
        }
        __syncthreads();

        int nk = kchunk4 >> 2;                    // BK16 iterations (16 or 8)
#pragma unroll 1
        for (int it = 0; it < nk; it++) {
            const float* As = dsm + (it & 1) * STAGE_F;
            const float* Bs = As + 16 * AS_STR;
            bool nxt = (it + 1 < nk);
            if (nxt) {
                int k4 = (it + 1) * 4;
#pragma unroll
                for (int r = 0; r < 2; r++) {
                    int mr = row + r * 64;
                    va[r] = g_H[s_src[mr] * E4 + aoff4 + k4 + c4];
                    vb[r] = W4[(n0 + mr) * 256 + woff4 + k4 + c4];
                }
            }
#pragma unroll
            for (int kk = 0; kk < 16; kk++) {
                const ulonglong2* ap =
                    (const ulonglong2*)&As[kk * AS_STR + ty * 16];
                ulonglong2 aA = ap[0], aB = ap[1], aC = ap[2], aD = ap[3];
                const ulonglong2* bp =
                    (const ulonglong2*)&Bs[kk * BS_STR + tx * 8];
                ulonglong2 b0 = bp[0], b1 = bp[1];
                unsigned long long a[8] = {aA.x, aA.y, aB.x, aB.y,
                                           aC.x, aC.y, aD.x, aD.y};
                unsigned long long b[4] = {b0.x, b0.y, b1.x, b1.y};
#pragma unroll
                for (int i = 0; i < 8; i++) {
                    fma2(acc[i][0], a[i], b[0]);
                    fma2(acc[i][1], a[i], b[1]);
                    fma2(acc[i][2], a[i], b[2]);
                    fma2(acc[i][3], a[i], b[3]);
                }
            }
            if (nxt) {
                float* As2 = dsm + ((it + 1) & 1) * STAGE_F;
                float* Bs2 = As2 + 16 * AS_STR;
#pragma unroll
                for (int r = 0; r < 2; r++) {
                    int mr = row + r * 64;
                    float av[4] = {va[r].x, va[r].y, va[r].z, va[r].w};
                    float bv[4] = {vb[r].x, vb[r].y, vb[r].z, vb[r].w};
#pragma unroll
                    for (int q = 0; q < 4; q++) {
                        *(unsigned long long*)&As2[(c4 * 4 + q) * AS_STR + 2 * mr] =
                            pk2(av[q], av[q]);
                        Bs2[(c4 * 4 + q) * BS_STR + mr] = bv[q];
                    }
                }
            }
            __syncthreads();
        }

        float4* pout = g_part + (size_t)z * MAXM * E4;
#pragma unroll
        for (int i = 0; i < 8; i++) {
            int m = bm * 128 + ty * 8 + i;
            if (m < cnt) {
                float2 p0 = upk2(acc[i][0]);
                float2 p1 = upk2(acc[i][1]);
                float2 p2 = upk2(acc[i][2]);
                float2 p3 = upk2(acc[i][3]);
                pout[m * E4 + (n0 >> 2) + tx * 2 + 0] = make_float4(p0.x, p0.y, p1.x, p1.y);
                pout[m * E4 + (n0 >> 2) + tx * 2 + 1] = make_float4(p2.x, p2.y, p3.x, p3.y);
            }
        }
        __syncthreads();
    }
}

// ---------------- combine partials + bias + relu -> H ----------------
__global__ void k_combine(int d, int ZS, const float4* __restrict__ bW4) {
    int cnt = g_cnt[d];
    const int* list = g_list[d];
    int total = cnt * E4;
    for (int idx = blockIdx.x * blockDim.x + threadIdx.x; idx < total;
         idx += gridDim.x * blockDim.x) {
        int m = idx >> 7, j = idx & 127;
        float4 s = g_part[m * E4 + j];
        for (int z = 1; z < ZS; z++) {
            float4 p = g_part[((size_t)z * MAXM + m) * E4 + j];
            s.x += p.x; s.y += p.y; s.z += p.z; s.w += p.w;
        }
        float4 b = bW4[j];
        s.x = fmaxf(s.x + b.x, 0.f);
        s.y = fmaxf(s.y + b.y, 0.f);
        s.z = fmaxf(s.z + b.z, 0.f);
        s.w = fmaxf(s.w + b.w, 0.f);
        g_H[list[m] * E4 + j] = s;
    }
}

// ---------------- fused deep tail: levels 8..13 in ONE kernel ------------
// grid = (32, 4) = 128 blocks (co-resident on 148 SMs); sense-reversing
// grid barrier between levels. Counters reset by k_zero every launch.
__device__ __forceinline__ void gbar(unsigned nb, unsigned& phase) {
    __threadfence();
    __syncthreads();
    if (threadIdx.x == 0) {
        unsigned t = atomicAdd(&g_arrive, 1u);
        if (t == phase * nb + (nb - 1)) {
            g_release = phase + 1;
        } else {
            while (g_release <= phase) { }
        }
        __threadfence();
    }
    __syncthreads();
    phase++;
}

__global__ __launch_bounds__(256) void k_tail(
    const int* __restrict__ left, const int* __restrict__ right,
    const float4* __restrict__ W4, const float* __restrict__ bW)
{
    __shared__ float4 pair[256];   // 1024 floats = [h_l ; h_r]
    int tid = threadIdx.x;
    int lane = tid & 31, w = tid >> 5;
    int n0 = blockIdx.y << 7;
    float* Hf = (float*)g_H;
    unsigned phase = 0;
    const unsigned NB = 32u * 4u;

#pragma unroll 1
    for (int d = 8; d <= 13; d++) {
        int cnt = g_cnt[d];
        if ((int)blockIdx.x < cnt) {
            int node = g_list[d][blockIdx.x];
            int cl = left[node], cr = right[node];
            pair[tid] = (tid < 128) ? g_H[cl * E4 + tid] : g_H[cr * E4 + tid - 128];
            __syncthreads();
#pragma unroll 1
            for (int o = 0; o < 16; o++) {
                int n = n0 + w * 16 + o;
                const float4* wrow = W4 + n * 256;
                float acc = 0.f;
#pragma unroll
                for (int it = 0; it < 8; it++) {
                    float4 wv = wrow[lane + it * 32];
                    float4 pv = pair[lane + it * 32];
                    acc += wv.x * pv.x + wv.y * pv.y + wv.z * pv.z + wv.w * pv.w;
                }
#pragma unroll
                for (int off = 16; off; off >>= 1)
                    acc += __shfl_xor_sync(0xffffffffu, acc, off);
                if (lane == 0)
                    Hf[node * EMBED + n] = fmaxf(acc + bW[n], 0.f);
            }
        }
        gbar(NB, phase);
    }
}

// ---------------- logits: out[i][c] = H[i] . P[c] + bP[c] ----------------
__global__ void k_logits(const float4* __restrict__ P4,
                         const float* __restrict__ bP,
                         float* __restrict__ out) {
    int gw = (blockIdx.x * blockDim.x + threadIdx.x) >> 5;
    int lane = threadIdx.x & 31;
    if (gw >= NNODES) return;
    float4 h[4];
#pragma unroll
    for (int i = 0; i < 4; i++) h[i] = g_H[gw * E4 + lane + i * 32];
#pragma unroll
    for (int c = 0; c < 5; c++) {
        float acc = 0.f;
#pragma unroll
        for (int i = 0; i < 4; i++) {
            float4 p = P4[c * E4 + lane + i * 32];
            acc += p.x * h[i].x + p.y * h[i].y + p.z * h[i].z + p.w * h[i].w;
        }
#pragma unroll
        for (int off = 16; off; off >>= 1)
            acc += __shfl_xor_sync(0xffffffffu, acc, off);
        if (lane == 0) out[gw * 5 + c] = acc + bP[c];
    }
}

// ---------------- launch ----------------
extern "C" void kernel_launch(void* const* d_in, const int* in_sizes, int n_in,
                              void* d_out, int out_size) {
    const int*   is_leaf = (const int*)d_in[0];
    const int*   word    = (const int*)d_in[1];
    const int*   left    = (const int*)d_in[2];
    const int*   right   = (const int*)d_in[3];
    const float* emb     = (const float*)d_in[4];
    const float* W       = (const float*)d_in[5];
    const float* bW      = (const float*)d_in[6];
    const float* P       = (const float*)d_in[7];
    const float* bP      = (const float*)d_in[8];
    float* out = (float*)d_out;

    cudaFuncSetAttribute(k_partial, cudaFuncAttributeMaxDynamicSharedMemorySize,
                         DYN_SMEM);

    k_zero<<<1, 32>>>();
    k_bucket<<<(NNODES + 255) / 256, 256>>>(is_leaf, left);
    k_leaf<<<(NNODES * 128 + 255) / 256, 256>>>(is_leaf, word, (const float4*)emb);

    for (int d = 1; d <= 7; d++) {
        int cnt = LEAVES >> d;   // expected level size (kernels read actual count)
        int ZS = (d <= 3) ? 4 : 8;
        int mt = (cnt + 127) / 128; if (mt < 1) mt = 1;
        k_partial<<<dim3(mt, 4, ZS), 256, DYN_SMEM>>>(d, ZS, left, right,
                                                      (const float4*)W);
        int cb = (cnt * 128 + 255) / 256; if (cb < 1) cb = 1;
        k_combine<<<cb, 256>>>(d, ZS, (const float4*)bW);
    }

    // levels 8..13 fused with grid-wide barrier
    k_tail<<<dim3(32, 4), 256>>>(left, right, (const float4*)W, bW);

    k_logits<<<(NNODES * 32 + 255) / 256, 256>>>((const float4*)P, bP, out);
}

// round 11
// speedup vs baseline: 1.1014x; 1.1014x over previous
#include <cuda_runtime.h>
#include <cstdint>

#define NNODES 16383
#define EMBED 512
#define E4 128          // float4 per H row
#define NLEV 16
#define LEAVES 8192
#define MAXM 4096

// ---------------- device scratch (static, no runtime alloc) ----------------
__device__ float4 g_H[NNODES * E4];          // 33.5 MB hidden states
__device__ float4 g_part[8 * MAXM * E4];     // 67 MB split-K partials
__device__ int    g_list[NLEV][MAXM];
__device__ int    g_cnt[NLEV];

// ---------------- f32x2 helpers ----------------
__device__ __forceinline__ void fma2(unsigned long long& d,
                                     unsigned long long a, unsigned long long b) {
    asm("fma.rn.f32x2 %0, %1, %2, %0;" : "+l"(d) : "l"(a), "l"(b));
}
__device__ __forceinline__ unsigned long long pk2(float x, float y) {
    unsigned long long r;
    asm("mov.b64 %0, {%1, %2};" : "=l"(r) : "f"(x), "f"(y));
    return r;
}
__device__ __forceinline__ float2 upk2(unsigned long long v) {
    float2 r;
    asm("mov.b64 {%0, %1}, %2;" : "=f"(r.x), "=f"(r.y) : "l"(v));
    return r;
}

// ---------------- schedule kernels ----------------
__global__ void k_zero() {
    if (threadIdx.x < NLEV) g_cnt[threadIdx.x] = 0;
}

__global__ void k_bucket(const int* __restrict__ is_leaf,
                         const int* __restrict__ left) {
    int i = blockIdx.x * blockDim.x + threadIdx.x;
    if (i >= NNODES) return;
    if (is_leaf[i]) return;
    int c = left[i];
    int d = 1;
    while (!is_leaf[c]) { c = left[c]; d++; if (d >= NLEV) break; }
    if (d >= NLEV) d = NLEV - 1;
    int slot = atomicAdd(&g_cnt[d], 1);
    if (slot < MAXM) g_list[d][slot] = i;
}

// ---------------- leaves: H[i] = relu(emb[word[i]]) ----------------
__global__ void k_leaf(const int* __restrict__ is_leaf,
                       const int* __restrict__ word,
                       const float4* __restrict__ emb4) {
    int t = blockIdx.x * blockDim.x + threadIdx.x;
    int node = t >> 7;
    if (node >= NNODES) return;
    if (!is_leaf[node]) return;
    int j = t & 127;
    float4 v = emb4[word[node] * E4 + j];
    v.x = fmaxf(v.x, 0.f); v.y = fmaxf(v.y, 0.f);
    v.z = fmaxf(v.z, 0.f); v.w = fmaxf(v.w, 0.f);
    g_H[node * E4 + j] = v;
}

// ---------------- FULL-K fused GEMM (d=1,2): no split-K, no combine -------
// BM=128, BN=64, 128 threads (16 ty x 8 tx), 8x8 micro-tile, K=1024 full.
// Epilogue: bias + relu -> g_H directly.
__global__ __launch_bounds__(128, 3) void k_full(
    int d, const int* __restrict__ left, const int* __restrict__ right,
    const float4* __restrict__ W4, const float* __restrict__ bW)
{
    __shared__ float As[16 * 132];   // [k][m] transposed, BM=128 (+4 pad)
    __shared__ float Bs[16 * 68];    // [k][n] transposed, BN=64 (+4 pad)
    __shared__ int s_node[128], s_srcL[128], s_srcR[128];

    int cnt = g_cnt[d];
    if (cnt == 0) return;
    const int* list = g_list[d];
    int tid = threadIdx.x;
    int tx = tid & 7, ty = tid >> 3;          // n = tx*8, m = ty*8
    int mtiles = (cnt + 127) >> 7;
    int tasks = mtiles * 8;

    for (int task = blockIdx.x; task < tasks; task += gridDim.x) {
        int bm = task >> 3;
        int n0 = (task & 7) << 6;             // float col base (0..448)

        {
            int m = bm * 128 + tid;
            int node = 0, sl = 0, sr = 0;
            if (m < cnt) { node = list[m]; sl = left[node]; sr = right[node]; }
            s_node[tid] = node; s_srcL[tid] = sl; s_srcR[tid] = sr;
        }
        __syncthreads();

        unsigned long long acc[8][4];
#pragma unroll
        for (int i = 0; i < 8; i++)
#pragma unroll
            for (int j = 0; j < 4; j++) acc[i][j] = 0ull;

        // prefetch chunk 0 (left child, koff 0)
        float4 va[4], vb[4];
        {
            const float4* arow = g_H + (size_t)s_srcL[tid] * E4;
#pragma unroll
            for (int q = 0; q < 4; q++) va[q] = arow[q];
            if (tid < 64) {
                const float4* brow = W4 + (size_t)(n0 + tid) * 256;
#pragma unroll
                for (int q = 0; q < 4; q++) vb[q] = brow[q];
            }
        }

#pragma unroll 1
        for (int c = 0; c < 64; c++) {        // 64 BK16 chunks over K=1024
            // STS transposed
#pragma unroll
            for (int q = 0; q < 4; q++) {
                As[(q * 4 + 0) * 132 + tid] = va[q].x;
                As[(q * 4 + 1) * 132 + tid] = va[q].y;
                As[(q * 4 + 2) * 132 + tid] = va[q].z;
                As[(q * 4 + 3) * 132 + tid] = va[q].w;
            }
            if (tid < 64) {
#pragma unroll
                for (int q = 0; q < 4; q++) {
                    Bs[(q * 4 + 0) * 68 + tid] = vb[q].x;
                    Bs[(q * 4 + 1) * 68 + tid] = vb[q].y;
                    Bs[(q * 4 + 2) * 68 + tid] = vb[q].z;
                    Bs[(q * 4 + 3) * 68 + tid] = vb[q].w;
                }
            }
            __syncthreads();

            // prefetch next chunk
            if (c + 1 < 64) {
                int cc = c + 1;
                const int* srcA = (cc < 32) ? s_srcL : s_srcR;
                int aoff = (cc & 31) * 4;
                const float4* arow = g_H + (size_t)srcA[tid] * E4 + aoff;
#pragma unroll
                for (int q = 0; q < 4; q++) va[q] = arow[q];
                if (tid < 64) {
                    const float4* brow = W4 + (size_t)(n0 + tid) * 256 + cc * 4;
#pragma unroll
                    for (int q = 0; q < 4; q++) vb[q] = brow[q];
                }
            }

#pragma unroll
            for (int kk = 0; kk < 16; kk++) {
                float4 a0 = *(const float4*)&As[kk * 132 + ty * 8];
                float4 a1 = *(const float4*)&As[kk * 132 + ty * 8 + 4];
                ulonglong2 bq0 = *(const ulonglong2*)&Bs[kk * 68 + tx * 8];
                ulonglong2 bq1 = *(const ulonglong2*)&Bs[kk * 68 + tx * 8 + 4];
                unsigned long long b[4] = {bq0.x, bq0.y, bq1.x, bq1.y};
                float a[8] = {a0.x, a0.y, a0.z, a0.w, a1.x, a1.y, a1.z, a1.w};
#pragma unroll
                for (int i = 0; i < 8; i++) {
                    unsigned long long ap = pk2(a[i], a[i]);
                    fma2(acc[i][0], ap, b[0]);
                    fma2(acc[i][1], ap, b[1]);
                    fma2(acc[i][2], ap, b[2]);
                    fma2(acc[i][3], ap, b[3]);
                }
            }
            __syncthreads();
        }

        // fused epilogue: bias + relu -> g_H
        float bias[8];
#pragma unroll
        for (int j = 0; j < 8; j++) bias[j] = bW[n0 + tx * 8 + j];
#pragma unroll
        for (int i = 0; i < 8; i++) {
            int lm = ty * 8 + i;
            int m = bm * 128 + lm;
            if (m < cnt) {
                int node = s_node[lm];
                float2 p0 = upk2(acc[i][0]);
                float2 p1 = upk2(acc[i][1]);
                float2 p2 = upk2(acc[i][2]);
                float2 p3 = upk2(acc[i][3]);
                float4 o0 = make_float4(fmaxf(p0.x + bias[0], 0.f),
                                        fmaxf(p0.y + bias[1], 0.f),
                                        fmaxf(p1.x + bias[2], 0.f),
                                        fmaxf(p1.y + bias[3], 0.f));
                float4 o1 = make_float4(fmaxf(p2.x + bias[4], 0.f),
                                        fmaxf(p2.y + bias[5], 0.f),
                                        fmaxf(p3.x + bias[6], 0.f),
                                        fmaxf(p3.y + bias[7], 0.f));
                g_H[(size_t)node * E4 + (n0 >> 2) + tx * 2 + 0] = o0;
                g_H[(size_t)node * E4 + (n0 >> 2) + tx * 2 + 1] = o1;
            }
        }
        __syncthreads();
    }
}

// ---------------- split-K GEMM partial (R9 proven, b-packs removed) -------
// BM=128, BN=128, BK=16, 256 threads, 8x8 micro-tile, f32x2 FMAs.
__global__ __launch_bounds__(256, 2) void k_partial(
    int d, int ZS,
    const int* __restrict__ left, const int* __restrict__ right,
    const float4* __restrict__ W4)
{
    int cnt = g_cnt[d];
    if (cnt == 0) return;
    const int* list = g_list[d];

    int z  = blockIdx.z;
    int n0 = blockIdx.y << 7;
    int kchunk4 = 256 / ZS;
    int aoff4 = (z & ((ZS >> 1) - 1)) * kchunk4;
    int woff4 = z * kchunk4;
    bool useRight = (z >= (ZS >> 1));

    __shared__ float As[16 * 132];
    __shared__ float Bs[16 * 132];
    __shared__ int s_src[128];

    int tid = threadIdx.x;
    int tx = tid & 15, ty = tid >> 4;
    int c4  = tid & 3;
    int row = tid >> 2;
    int mtiles = (cnt + 127) >> 7;

    for (int bm = blockIdx.x; bm < mtiles; bm += gridDim.x) {
        if (tid < 128) {
            int m = bm * 128 + tid;
            int src = 0;
            if (m < cnt) {
                int node = list[m];
                src = useRight ? right[node] : left[node];
            }
            s_src[tid] = src;
        }
        __syncthreads();

        unsigned long long acc[8][4];
#pragma unroll
        for (int i = 0; i < 8; i++)
#pragma unroll
            for (int j = 0; j < 4; j++) acc[i][j] = 0ull;

        float4 va[2], vb[2];
#pragma unroll
        for (int r = 0; r < 2; r++) {
            int mr = row + r * 64;
            va[r] = g_H[s_src[mr] * E4 + aoff4 + c4];
            vb[r] = W4[(n0 + mr) * 256 + woff4 + c4];
        }

        for (int k4 = 0; k4 < kchunk4; k4 += 4) {
#pragma unroll
            for (int r = 0; r < 2; r++) {
                int mr = row + r * 64;
                As[(c4 * 4 + 0) * 132 + mr] = va[r].x;
                As[(c4 * 4 + 1) * 132 + mr] = va[r].y;
                As[(c4 * 4 + 2) * 132 + mr] = va[r].z;
                As[(c4 * 4 + 3) * 132 + mr] = va[r].w;
                Bs[(c4 * 4 + 0) * 132 + mr] = vb[r].x;
                Bs[(c4 * 4 + 1) * 132 + mr] = vb[r].y;
                Bs[(c4 * 4 + 2) * 132 + mr] = vb[r].z;
                Bs[(c4 * 4 + 3) * 132 + mr] = vb[r].w;
            }
            __syncthreads();

            if (k4 + 4 < kchunk4) {
#pragma unroll
                for (int r = 0; r < 2; r++) {
                    int mr = row + r * 64;
                    va[r] = g_H[s_src[mr] * E4 + aoff4 + k4 + 4 + c4];
                    vb[r] = W4[(n0 + mr) * 256 + woff4 + k4 + 4 + c4];
                }
            }

#pragma unroll
            for (int kk = 0; kk < 16; kk++) {
                float4 a0 = *(const float4*)&As[kk * 132 + ty * 8];
                float4 a1 = *(const float4*)&As[kk * 132 + ty * 8 + 4];
                ulonglong2 bq0 = *(const ulonglong2*)&Bs[kk * 132 + tx * 8];
                ulonglong2 bq1 = *(const ulonglong2*)&Bs[kk * 132 + tx * 8 + 4];
                unsigned long long b[4] = {bq0.x, bq0.y, bq1.x, bq1.y};
                float a[8] = {a0.x, a0.y, a0.z, a0.w, a1.x, a1.y, a1.z, a1.w};
#pragma unroll
                for (int i = 0; i < 8; i++) {
                    unsigned long long ap = pk2(a[i], a[i]);
                    fma2(acc[i][0], ap, b[0]);
                    fma2(acc[i][1], ap, b[1]);
                    fma2(acc[i][2], ap, b[2]);
                    fma2(acc[i][3], ap, b[3]);
                }
            }
            __syncthreads();
        }

        float4* pout = g_part + (size_t)z * MAXM * E4;
#pragma unroll
        for (int i = 0; i < 8; i++) {
            int m = bm * 128 + ty * 8 + i;
            if (m < cnt) {
                float2 p0 = upk2(acc[i][0]);
                float2 p1 = upk2(acc[i][1]);
                float2 p2 = upk2(acc[i][2]);
                float2 p3 = upk2(acc[i][3]);
                pout[m * E4 + (n0 >> 2) + tx * 2 + 0] = make_float4(p0.x, p0.y, p1.x, p1.y);
                pout[m * E4 + (n0 >> 2) + tx * 2 + 1] = make_float4(p2.x, p2.y, p3.x, p3.y);
            }
        }
        __syncthreads();
    }
}

// ---------------- combine partials + bias + relu -> H ----------------
__global__ void k_combine(int d, int ZS, const float4* __restrict__ bW4) {
    int cnt = g_cnt[d];
    const int* list = g_list[d];
    int total = cnt * E4;
    for (int idx = blockIdx.x * blockDim.x + threadIdx.x; idx < total;
         idx += gridDim.x * blockDim.x) {
        int m = idx >> 7, j = idx & 127;
        float4 s = g_part[m * E4 + j];
        for (int z = 1; z < ZS; z++) {
            float4 p = g_part[((size_t)z * MAXM + m) * E4 + j];
            s.x += p.x; s.y += p.y; s.z += p.z; s.w += p.w;
        }
        float4 b = bW4[j];
        s.x = fmaxf(s.x + b.x, 0.f);
        s.y = fmaxf(s.y + b.y, 0.f);
        s.z = fmaxf(s.z + b.z, 0.f);
        s.w = fmaxf(s.w + b.w, 0.f);
        g_H[list[m] * E4 + j] = s;
    }
}

// ---------------- small levels (<=32 nodes): warp-per-output ----------------
__global__ __launch_bounds__(256) void k_small(
    int d, const int* __restrict__ left, const int* __restrict__ right,
    const float4* __restrict__ W4, const float* __restrict__ bW)
{
    int cnt = g_cnt[d];
    __shared__ float4 pair[256];   // 1024 floats = [h_l ; h_r]
    int tid = threadIdx.x;
    int lane = tid & 31, w = tid >> 5;
    int n0 = blockIdx.y << 7;      // 128 outputs per block
    float* Hf = (float*)g_H;

    for (int bx = blockIdx.x; bx < cnt; bx += gridDim.x) {
        int node = g_list[d][bx];
        int cl = left[node], cr = right[node];
        __syncthreads();
        pair[tid] = (tid < 128) ? g_H[cl * E4 + tid] : g_H[cr * E4 + tid - 128];
        __syncthreads();
#pragma unroll 1
        for (int o = 0; o < 16; o++) {
            int n = n0 + w * 16 + o;
            const float4* wrow = W4 + n * 256;
            float acc = 0.f;
#pragma unroll
            for (int it = 0; it < 8; it++) {
                float4 wv = wrow[lane + it * 32];
                float4 pv = pair[lane + it * 32];
                acc += wv.x * pv.x + wv.y * pv.y + wv.z * pv.z + wv.w * pv.w;
            }
#pragma unroll
            for (int off = 16; off; off >>= 1)
                acc += __shfl_xor_sync(0xffffffffu, acc, off);
            if (lane == 0)
                Hf[node * EMBED + n] = fmaxf(acc + bW[n], 0.f);
        }
    }
}

// ---------------- logits: out[i][c] = H[i] . P[c] + bP[c] ----------------
__global__ void k_logits(const float4* __restrict__ P4,
                         const float* __restrict__ bP,
                         float* __restrict__ out) {
    int gw = (blockIdx.x * blockDim.x + threadIdx.x) >> 5;
    int lane = threadIdx.x & 31;
    if (gw >= NNODES) return;
    float4 h[4];
#pragma unroll
    for (int i = 0; i < 4; i++) h[i] = g_H[gw * E4 + lane + i * 32];
#pragma unroll
    for (int c = 0; c < 5; c++) {
        float acc = 0.f;
#pragma unroll
        for (int i = 0; i < 4; i++) {
            float4 p = P4[c * E4 + lane + i * 32];
            acc += p.x * h[i].x + p.y * h[i].y + p.z * h[i].z + p.w * h[i].w;
        }
#pragma unroll
        for (int off = 16; off; off >>= 1)
            acc += __shfl_xor_sync(0xffffffffu, acc, off);
        if (lane == 0) out[gw * 5 + c] = acc + bP[c];
    }
}

// ---------------- launch ----------------
extern "C" void kernel_launch(void* const* d_in, const int* in_sizes, int n_in,
                              void* d_out, int out_size) {
    const int*   is_leaf = (const int*)d_in[0];
    const int*   word    = (const int*)d_in[1];
    const int*   left    = (const int*)d_in[2];
    const int*   right   = (const int*)d_in[3];
    const float* emb     = (const float*)d_in[4];
    const float* W       = (const float*)d_in[5];
    const float* bW      = (const float*)d_in[6];
    const float* P       = (const float*)d_in[7];
    const float* bP      = (const float*)d_in[8];
    float* out = (float*)d_out;

    k_zero<<<1, 32>>>();
    k_bucket<<<(NNODES + 255) / 256, 256>>>(is_leaf, left);
    k_leaf<<<(NNODES * 128 + 255) / 256, 256>>>(is_leaf, word, (const float4*)emb);

    // d=1,2: full-K fused GEMM (no split-K, no combine)
    for (int d = 1; d <= 2; d++) {
        int cnt = LEAVES >> d;
        int tasks = ((cnt + 127) / 128) * 8;
        k_full<<<tasks, 128>>>(d, left, right, (const float4*)W, bW);
    }

    // d=3..7: split-K + combine (proven path)
    for (int d = 3; d <= 7; d++) {
        int cnt = LEAVES >> d;
        int ZS = (d == 3) ? 4 : 8;
        int mt = (cnt + 127) / 128; if (mt < 1) mt = 1;
        k_partial<<<dim3(mt, 4, ZS), 256>>>(d, ZS, left, right, (const float4*)W);
        int cb = (cnt * 128 + 255) / 256; if (cb < 1) cb = 1;
        k_combine<<<cb, 256>>>(d, ZS, (const float4*)bW);
    }

    // d=8..13: warp-per-output
    for (int d = 8; d <= 13; d++) {
        int cnt = LEAVES >> d;
        int gx = cnt < 1 ? 1 : cnt;
        k_small<<<dim3(gx, 4), 256>>>(d, left, right, (const float4*)W, bW);
    }

    k_logits<<<(NNODES * 32 + 255) / 256, 256>>>((const float4*)P, bP, out);
}

// round 13
// speedup vs baseline: 1.4083x; 1.2786x over previous
#include <cuda_runtime.h>
#include <cstdint>

#define NNODES 16383
#define EMBED 512
#define E4 128          // float4 per H row
#define NLEV 16
#define LEAVES 8192
#define MAXM 4096

// ---------------- device scratch (static, no runtime alloc) ----------------
__device__ float4 g_H[NNODES * E4];          // 33.5 MB hidden states
__device__ float4 g_part[8 * MAXM * E4];     // 67 MB split-K partials
__device__ int    g_list[NLEV][MAXM];
__device__ int    g_cnt[NLEV];

// ---------------- f32x2 helpers ----------------
__device__ __forceinline__ void fma2(unsigned long long& d,
                                     unsigned long long a, unsigned long long b) {
    asm("fma.rn.f32x2 %0, %1, %2, %0;" : "+l"(d) : "l"(a), "l"(b));
}
__device__ __forceinline__ unsigned long long pk2(float x, float y) {
    unsigned long long r;
    asm("mov.b64 %0, {%1, %2};" : "=l"(r) : "f"(x), "f"(y));
    return r;
}
__device__ __forceinline__ float2 upk2(unsigned long long v) {
    float2 r;
    asm("mov.b64 {%0, %1}, %2;" : "=f"(r.x), "=f"(r.y) : "l"(v));
    return r;
}

// ---------------- schedule kernels ----------------
__global__ void k_zero() {
    if (threadIdx.x < NLEV) g_cnt[threadIdx.x] = 0;
}

__global__ void k_bucket(const int* __restrict__ is_leaf,
                         const int* __restrict__ left) {
    int i = blockIdx.x * blockDim.x + threadIdx.x;
    if (i >= NNODES) return;
    if (is_leaf[i]) return;
    int c = left[i];
    int d = 1;
    while (!is_leaf[c]) { c = left[c]; d++; if (d >= NLEV) break; }
    if (d >= NLEV) d = NLEV - 1;
    int slot = atomicAdd(&g_cnt[d], 1);
    if (slot < MAXM) g_list[d][slot] = i;
}

// ---------------- leaves: H[i] = relu(emb[word[i]]) ----------------
__global__ void k_leaf(const int* __restrict__ is_leaf,
                       const int* __restrict__ word,
                       const float4* __restrict__ emb4) {
    int t = blockIdx.x * blockDim.x + threadIdx.x;
    int node = t >> 7;
    if (node >= NNODES) return;
    if (!is_leaf[node]) return;
    int j = t & 127;
    float4 v = emb4[word[node] * E4 + j];
    v.x = fmaxf(v.x, 0.f); v.y = fmaxf(v.y, 0.f);
    v.z = fmaxf(v.z, 0.f); v.w = fmaxf(v.w, 0.f);
    g_H[node * E4 + j] = v;
}

// ---------------- split-K GEMM partial ----------------
// BM=128, BN=128, BK=16, 256 threads, 8x8 micro-tile, f32x2 FMAs.
// Conflict-free read mapping: warp tile 32m x 64n (warps 4x2);
// lane = (m_lane 0..3, n_lane 0..7).
//   A frags: m_lane*4 and +16  -> banks 0-15 / 16-31, 8-way bcast, CF.
//   B frags: n_lane*4 and +32  -> banks {0,4,..,28}, 4-way bcast, CF.
__global__ __launch_bounds__(256, 2) void k_partial(
    int d, int ZS,
    const int* __restrict__ left, const int* __restrict__ right,
    const float4* __restrict__ W4)
{
    int cnt = g_cnt[d];
    if (cnt == 0) return;
    const int* list = g_list[d];

    int z  = blockIdx.z;
    int n0 = blockIdx.y << 7;           // output-col tile base (0..384)
    int kchunk4 = 256 / ZS;             // float4s per K chunk (64 or 32)
    int aoff4 = (z & ((ZS >> 1) - 1)) * kchunk4;   // within-child col (f4)
    int woff4 = z * kchunk4;                        // within-W col (f4)
    bool useRight = (z >= (ZS >> 1));

    __shared__ float As[16 * 132];
    __shared__ float Bs[16 * 132];
    __shared__ int s_src[128];

    int tid = threadIdx.x;
    int lane = tid & 31, w = tid >> 5;
    int wm = w & 3, wn = w >> 2;        // warp grid 4(m) x 2(n)
    int m_lane = lane & 3, n_lane = lane >> 2;
    int am0 = wm * 32 + m_lane * 4;     // A frag base (+0..3, +16)
    int bn0 = wn * 64 + n_lane * 4;     // B frag base (+0..3, +32)

    int c4  = tid & 3;                  // k-f4 chunk within BK tile (store side)
    int row = tid >> 2;                 // 0..63 (row index for loading)
    int mtiles = (cnt + 127) >> 7;

    for (int bm = blockIdx.x; bm < mtiles; bm += gridDim.x) {
        if (tid < 128) {
            int m = bm * 128 + tid;
            int src = 0;
            if (m < cnt) {
                int node = list[m];
                src = useRight ? right[node] : left[node];
            }
            s_src[tid] = src;
        }
        __syncthreads();

        unsigned long long acc[8][4];
#pragma unroll
        for (int i = 0; i < 8; i++)
#pragma unroll
            for (int j = 0; j < 4; j++) acc[i][j] = 0ull;

        // prefetch chunk 0 into registers
        float4 va[2], vb[2];
#pragma unroll
        for (int r = 0; r < 2; r++) {
            int mr = row + r * 64;
            va[r] = g_H[s_src[mr] * E4 + aoff4 + c4];
            vb[r] = W4[(n0 + mr) * 256 + woff4 + c4];
        }

        for (int k4 = 0; k4 < kchunk4; k4 += 4) {   // BK = 16 floats
            // store staged chunk to smem (transposed [k][m] / [k][n])
#pragma unroll
            for (int r = 0; r < 2; r++) {
                int mr = row + r * 64;
                As[(c4 * 4 + 0) * 132 + mr] = va[r].x;
                As[(c4 * 4 + 1) * 132 + mr] = va[r].y;
                As[(c4 * 4 + 2) * 132 + mr] = va[r].z;
                As[(c4 * 4 + 3) * 132 + mr] = va[r].w;
                Bs[(c4 * 4 + 0) * 132 + mr] = vb[r].x;
                Bs[(c4 * 4 + 1) * 132 + mr] = vb[r].y;
                Bs[(c4 * 4 + 2) * 132 + mr] = vb[r].z;
                Bs[(c4 * 4 + 3) * 132 + mr] = vb[r].w;
            }
            __syncthreads();

            // prefetch next chunk while computing this one
            if (k4 + 4 < kchunk4) {
#pragma unroll
                for (int r = 0; r < 2; r++) {
                    int mr = row + r * 64;
                    va[r] = g_H[s_src[mr] * E4 + aoff4 + k4 + 4 + c4];
                    vb[r] = W4[(n0 + mr) * 256 + woff4 + k4 + 4 + c4];
                }
            }

#pragma unroll
            for (int kk = 0; kk < 16; kk++) {
                float4 a0 = *(const float4*)&As[kk * 132 + am0];
                float4 a1 = *(const float4*)&As[kk * 132 + am0 + 16];
                ulonglong2 bq0 = *(const ulonglong2*)&Bs[kk * 132 + bn0];
                ulonglong2 bq1 = *(const ulonglong2*)&Bs[kk * 132 + bn0 + 32];
                unsigned long long b[4] = {bq0.x, bq0.y, bq1.x, bq1.y};
                float a[8] = {a0.x, a0.y, a0.z, a0.w, a1.x, a1.y, a1.z, a1.w};
#pragma unroll
                for (int i = 0; i < 8; i++) {
                    unsigned long long ap = pk2(a[i], a[i]);
                    fma2(acc[i][0], ap, b[0]);
                    fma2(acc[i][1], ap, b[1]);
                    fma2(acc[i][2], ap, b[2]);
                    fma2(acc[i][3], ap, b[3]);
                }
            }
            __syncthreads();
        }

        float4* pout = g_part + (size_t)z * MAXM * E4;
#pragma unroll
        for (int i = 0; i < 8; i++) {
            int lm = am0 + (i & 3) + ((i >> 2) << 4);   // local m row
            int m = bm * 128 + lm;
            if (m < cnt) {
                float2 p0 = upk2(acc[i][0]);
                float2 p1 = upk2(acc[i][1]);
                float2 p2 = upk2(acc[i][2]);
                float2 p3 = upk2(acc[i][3]);
                pout[m * E4 + (n0 >> 2) + (bn0 >> 2)    ] = make_float4(p0.x, p0.y, p1.x, p1.y);
                pout[m * E4 + (n0 >> 2) + (bn0 >> 2) + 8] = make_float4(p2.x, p2.y, p3.x, p3.y);
            }
        }
        __syncthreads();
    }
}

// ---------------- combine partials + bias + relu -> H ----------------
__global__ void k_combine(int d, int ZS, const float4* __restrict__ bW4) {
    int cnt = g_cnt[d];
    const int* list = g_list[d];
    int total = cnt * E4;
    for (int idx = blockIdx.x * blockDim.x + threadIdx.x; idx < total;
         idx += gridDim.x * blockDim.x) {
        int m = idx >> 7, j = idx & 127;
        float4 s = g_part[m * E4 + j];
        for (int z = 1; z < ZS; z++) {
            float4 p = g_part[((size_t)z * MAXM + m) * E4 + j];
            s.x += p.x; s.y += p.y; s.z += p.z; s.w += p.w;
        }
        float4 b = bW4[j];
        s.x = fmaxf(s.x + b.x, 0.f);
        s.y = fmaxf(s.y + b.y, 0.f);
        s.z = fmaxf(s.z + b.z, 0.f);
        s.w = fmaxf(s.w + b.w, 0.f);
        g_H[list[m] * E4 + j] = s;
    }
}

// ---------------- small levels (<=32 nodes): warp-per-output ----------------
__global__ __launch_bounds__(256) void k_small(
    int d, const int* __restrict__ left, const int* __restrict__ right,
    const float4* __restrict__ W4, const float* __restrict__ bW)
{
    int cnt = g_cnt[d];
    __shared__ float4 pair[256];   // 1024 floats = [h_l ; h_r]
    int tid = threadIdx.x;
    int lane = tid & 31, w = tid >> 5;
    int n0 = blockIdx.y << 7;      // 128 outputs per block
    float* Hf = (float*)g_H;

    for (int bx = blockIdx.x; bx < cnt; bx += gridDim.x) {
        int node = g_list[d][bx];
        int cl = left[node], cr = right[node];
        __syncthreads();
        pair[tid] = (tid < 128) ? g_H[cl * E4 + tid] : g_H[cr * E4 + tid - 128];
        __syncthreads();
#pragma unroll 1
        for (int o = 0; o < 16; o++) {
            int n = n0 + w * 16 + o;
            const float4* wrow = W4 + n * 256;
            float acc = 0.f;
#pragma unroll
            for (int it = 0; it < 8; it++) {
                float4 wv = wrow[lane + it * 32];
                float4 pv = pair[lane + it * 32];
                acc += wv.x * pv.x + wv.y * pv.y + wv.z * pv.z + wv.w * pv.w;
            }
#pragma unroll
            for (int off = 16; off; off >>= 1)
                acc += __shfl_xor_sync(0xffffffffu, acc, off);
            if (lane == 0)
                Hf[node * EMBED + n] = fmaxf(acc + bW[n], 0.f);
        }
    }
}

// ---------------- logits: out[i][c] = H[i] . P[c] + bP[c] ----------------
__global__ void k_logits(const float4* __restrict__ P4,
                         const float* __restrict__ bP,
                         float* __restrict__ out) {
    int gw = (blockIdx.x * blockDim.x + threadIdx.x) >> 5;
    int lane = threadIdx.x & 31;
    if (gw >= NNODES) return;
    float4 h[4];
#pragma unroll
    for (int i = 0; i < 4; i++) h[i] = g_H[gw * E4 + lane + i * 32];
#pragma unroll
    for (int c = 0; c < 5; c++) {
        float acc = 0.f;
#pragma unroll
        for (int i = 0; i < 4; i++) {
            float4 p = P4[c * E4 + lane + i * 32];
            acc += p.x * h[i].x + p.y * h[i].y + p.z * h[i].z + p.w * h[i].w;
        }
#pragma unroll
        for (int off = 16; off; off >>= 1)
            acc += __shfl_xor_sync(0xffffffffu, acc, off);
        if (lane == 0) out[gw * 5 + c] = acc + bP[c];
    }
}

// ---------------- launch ----------------
extern "C" void kernel_launch(void* const* d_in, const int* in_sizes, int n_in,
                              void* d_out, int out_size) {
    const int*   is_leaf = (const int*)d_in[0];
    const int*   word    = (const int*)d_in[1];
    const int*   left    = (const int*)d_in[2];
    const int*   right   = (const int*)d_in[3];
    const float* emb     = (const float*)d_in[4];
    const float* W       = (const float*)d_in[5];
    const float* bW      = (const float*)d_in[6];
    const float* P       = (const float*)d_in[7];
    const float* bP      = (const float*)d_in[8];
    float* out = (float*)d_out;

    k_zero<<<1, 32>>>();
    k_bucket<<<(NNODES + 255) / 256, 256>>>(is_leaf, left);
    k_leaf<<<(NNODES * 128 + 255) / 256, 256>>>(is_leaf, word, (const float4*)emb);

    for (int d = 1; d <= 13; d++) {
        int cnt = LEAVES >> d;   // expected level size (kernels read actual count)
        if (cnt >= 64) {
            int ZS = (d <= 3) ? 4 : 8;
            int mt = (cnt + 127) / 128; if (mt < 1) mt = 1;
            k_partial<<<dim3(mt, 4, ZS), 256>>>(d, ZS, left, right, (const float4*)W);
            int cb = (cnt * 128 + 255) / 256; if (cb < 1) cb = 1;
            k_combine<<<cb, 256>>>(d, ZS, (const float4*)bW);
        } else {
            int gx = cnt < 1 ? 1 : cnt;
            k_small<<<dim3(gx, 4), 256>>>(d, left, right, (const float4*)W, bW);
        }
    }

    k_logits<<<(NNODES * 32 + 255) / 256, 256>>>((const float4*)P, bP, out);
}

// round 14
// speedup vs baseline: 1.4605x; 1.0371x over previous
#include <cuda_runtime.h>
#include <cstdint>

#define NNODES 16383
#define EMBED 512
#define E4 128          // float4 per H row
#define NLEV 16
#define LEAVES 8192
#define MAXM 4096

// ---------------- device scratch (static, no runtime alloc) ----------------
__device__ float4 g_H[NNODES * E4];          // 33.5 MB hidden states
__device__ float4 g_part[8 * MAXM * E4];     // 67 MB split-K partials
__device__ int    g_list[NLEV][MAXM];
__device__ int    g_cnt[NLEV];

// ---------------- f32x2 helpers ----------------
__device__ __forceinline__ void fma2(unsigned long long& d,
                                     unsigned long long a, unsigned long long b) {
    asm("fma.rn.f32x2 %0, %1, %2, %0;" : "+l"(d) : "l"(a), "l"(b));
}
__device__ __forceinline__ unsigned long long pk2(float x, float y) {
    unsigned long long r;
    asm("mov.b64 %0, {%1, %2};" : "=l"(r) : "f"(x), "f"(y));
    return r;
}
__device__ __forceinline__ float2 upk2(unsigned long long v) {
    float2 r;
    asm("mov.b64 {%0, %1}, %2;" : "=f"(r.x), "=f"(r.y) : "l"(v));
    return r;
}

// ---------------- schedule kernels ----------------
__global__ void k_zero() {
    if (threadIdx.x < NLEV) g_cnt[threadIdx.x] = 0;
}

__global__ void k_bucket(const int* __restrict__ is_leaf,
                         const int* __restrict__ left) {
    int i = blockIdx.x * blockDim.x + threadIdx.x;
    if (i >= NNODES) return;
    if (is_leaf[i]) return;
    int c = left[i];
    int d = 1;
    while (!is_leaf[c]) { c = left[c]; d++; if (d >= NLEV) break; }
    if (d >= NLEV) d = NLEV - 1;
    int slot = atomicAdd(&g_cnt[d], 1);
    if (slot < MAXM) g_list[d][slot] = i;
}

// ---------------- leaves: H[i] = relu(emb[word[i]]) ----------------
__global__ void k_leaf(const int* __restrict__ is_leaf,
                       const int* __restrict__ word,
                       const float4* __restrict__ emb4) {
    int t = blockIdx.x * blockDim.x + threadIdx.x;
    int node = t >> 7;
    if (node >= NNODES) return;
    if (!is_leaf[node]) return;
    int j = t & 127;
    float4 v = emb4[word[node] * E4 + j];
    v.x = fmaxf(v.x, 0.f); v.y = fmaxf(v.y, 0.f);
    v.z = fmaxf(v.z, 0.f); v.w = fmaxf(v.w, 0.f);
    g_H[node * E4 + j] = v;
}

// ---------------- split-K GEMM partial ----------------
// BM=128, BN=128, BK=16, 256 threads, 8x8 micro-tile, f32x2 FMAs.
// Conflict-free read mapping (R13): warp tile 32m x 64n (warps 4x2);
// lane = (m_lane 0..3, n_lane 0..7).
//   A frags: m_lane*4 and +16  -> conflict-free w/ broadcast.
//   B frags: n_lane*4 and +32  -> conflict-free w/ broadcast.
// NEW: double-buffered smem stages -> ONE __syncthreads per BK chunk.
#define STAGE_F (16 * 132)

__global__ __launch_bounds__(256, 2) void k_partial(
    int d, int ZS,
    const int* __restrict__ left, const int* __restrict__ right,
    const float4* __restrict__ W4)
{
    int cnt = g_cnt[d];
    if (cnt == 0) return;
    const int* list = g_list[d];

    int z  = blockIdx.z;
    int n0 = blockIdx.y << 7;           // output-col tile base (0..384)
    int kchunk4 = 256 / ZS;             // float4s per K chunk (64 or 32)
    int aoff4 = (z & ((ZS >> 1) - 1)) * kchunk4;   // within-child col (f4)
    int woff4 = z * kchunk4;                        // within-W col (f4)
    bool useRight = (z >= (ZS >> 1));

    __shared__ float As[2][STAGE_F];
    __shared__ float Bs[2][STAGE_F];
    __shared__ int s_src[128];

    int tid = threadIdx.x;
    int lane = tid & 31, w = tid >> 5;
    int wm = w & 3, wn = w >> 2;        // warp grid 4(m) x 2(n)
    int m_lane = lane & 3, n_lane = lane >> 2;
    int am0 = wm * 32 + m_lane * 4;     // A frag base (+0..3, +16)
    int bn0 = wn * 64 + n_lane * 4;     // B frag base (+0..3, +32)

    int c4  = tid & 3;                  // k-f4 chunk within BK tile (store side)
    int row = tid >> 2;                 // 0..63 (row index for loading)
    int mtiles = (cnt + 127) >> 7;

    for (int bm = blockIdx.x; bm < mtiles; bm += gridDim.x) {
        if (tid < 128) {
            int m = bm * 128 + tid;
            int src = 0;
            if (m < cnt) {
                int node = list[m];
                src = useRight ? right[node] : left[node];
            }
            s_src[tid] = src;
        }
        __syncthreads();

        unsigned long long acc[8][4];
#pragma unroll
        for (int i = 0; i < 8; i++)
#pragma unroll
            for (int j = 0; j < 4; j++) acc[i][j] = 0ull;

        // prologue: LDG chunk 0, STS into stage 0, one sync
        float4 va[2], vb[2];
#pragma unroll
        for (int r = 0; r < 2; r++) {
            int mr = row + r * 64;
            va[r] = g_H[s_src[mr] * E4 + aoff4 + c4];
            vb[r] = W4[(n0 + mr) * 256 + woff4 + c4];
        }
#pragma unroll
        for (int r = 0; r < 2; r++) {
            int mr = row + r * 64;
            As[0][(c4 * 4 + 0) * 132 + mr] = va[r].x;
            As[0][(c4 * 4 + 1) * 132 + mr] = va[r].y;
            As[0][(c4 * 4 + 2) * 132 + mr] = va[r].z;
            As[0][(c4 * 4 + 3) * 132 + mr] = va[r].w;
            Bs[0][(c4 * 4 + 0) * 132 + mr] = vb[r].x;
            Bs[0][(c4 * 4 + 1) * 132 + mr] = vb[r].y;
            Bs[0][(c4 * 4 + 2) * 132 + mr] = vb[r].z;
            Bs[0][(c4 * 4 + 3) * 132 + mr] = vb[r].w;
        }
        __syncthreads();

        int nk = kchunk4 >> 2;          // BK16 chunks (16 or 8)
#pragma unroll 1
        for (int it = 0; it < nk; it++) {
            int cur = it & 1, nxt = cur ^ 1;
            bool more = (it + 1 < nk);
            // prefetch next chunk into registers (LDG latency hides under compute)
            if (more) {
                int k4 = (it + 1) * 4;
#pragma unroll
                for (int r = 0; r < 2; r++) {
                    int mr = row + r * 64;
                    va[r] = g_H[s_src[mr] * E4 + aoff4 + k4 + c4];
                    vb[r] = W4[(n0 + mr) * 256 + woff4 + k4 + c4];
                }
            }

            // compute current stage
#pragma unroll
            for (int kk = 0; kk < 16; kk++) {
                float4 a0 = *(const float4*)&As[cur][kk * 132 + am0];
                float4 a1 = *(const float4*)&As[cur][kk * 132 + am0 + 16];
                ulonglong2 bq0 = *(const ulonglong2*)&Bs[cur][kk * 132 + bn0];
                ulonglong2 bq1 = *(const ulonglong2*)&Bs[cur][kk * 132 + bn0 + 32];
                unsigned long long b[4] = {bq0.x, bq0.y, bq1.x, bq1.y};
                float a[8] = {a0.x, a0.y, a0.z, a0.w, a1.x, a1.y, a1.z, a1.w};
#pragma unroll
                for (int i = 0; i < 8; i++) {
                    unsigned long long ap = pk2(a[i], a[i]);
                    fma2(acc[i][0], ap, b[0]);
                    fma2(acc[i][1], ap, b[1]);
                    fma2(acc[i][2], ap, b[2]);
                    fma2(acc[i][3], ap, b[3]);
                }
            }

            // stage the prefetched chunk into the other buffer
            if (more) {
#pragma unroll
                for (int r = 0; r < 2; r++) {
                    int mr = row + r * 64;
                    As[nxt][(c4 * 4 + 0) * 132 + mr] = va[r].x;
                    As[nxt][(c4 * 4 + 1) * 132 + mr] = va[r].y;
                    As[nxt][(c4 * 4 + 2) * 132 + mr] = va[r].z;
                    As[nxt][(c4 * 4 + 3) * 132 + mr] = va[r].w;
                    Bs[nxt][(c4 * 4 + 0) * 132 + mr] = vb[r].x;
                    Bs[nxt][(c4 * 4 + 1) * 132 + mr] = vb[r].y;
                    Bs[nxt][(c4 * 4 + 2) * 132 + mr] = vb[r].z;
                    Bs[nxt][(c4 * 4 + 3) * 132 + mr] = vb[r].w;
                }
            }
            __syncthreads();            // one barrier per chunk
        }

        float4* pout = g_part + (size_t)z * MAXM * E4;
#pragma unroll
        for (int i = 0; i < 8; i++) {
            int lm = am0 + (i & 3) + ((i >> 2) << 4);   // local m row
            int m = bm * 128 + lm;
            if (m < cnt) {
                float2 p0 = upk2(acc[i][0]);
                float2 p1 = upk2(acc[i][1]);
                float2 p2 = upk2(acc[i][2]);
                float2 p3 = upk2(acc[i][3]);
                pout[m * E4 + (n0 >> 2) + (bn0 >> 2)    ] = make_float4(p0.x, p0.y, p1.x, p1.y);
                pout[m * E4 + (n0 >> 2) + (bn0 >> 2) + 8] = make_float4(p2.x, p2.y, p3.x, p3.y);
            }
        }
        __syncthreads();
    }
}

// ---------------- combine partials + bias + relu -> H ----------------
__global__ void k_combine(int d, int ZS, const float4* __restrict__ bW4) {
    int cnt = g_cnt[d];
    const int* list = g_list[d];
    int total = cnt * E4;
    for (int idx = blockIdx.x * blockDim.x + threadIdx.x; idx < total;
         idx += gridDim.x * blockDim.x) {
        int m = idx >> 7, j = idx & 127;
        float4 s = g_part[m * E4 + j];
        for (int z = 1; z < ZS; z++) {
            float4 p = g_part[((size_t)z * MAXM + m) * E4 + j];
            s.x += p.x; s.y += p.y; s.z += p.z; s.w += p.w;
        }
        float4 b = bW4[j];
        s.x = fmaxf(s.x + b.x, 0.f);
        s.y = fmaxf(s.y + b.y, 0.f);
        s.z = fmaxf(s.z + b.z, 0.f);
        s.w = fmaxf(s.w + b.w, 0.f);
        g_H[list[m] * E4 + j] = s;
    }
}

// ---------------- small levels (<=32 nodes): warp-per-output ----------------
__global__ __launch_bounds__(256) void k_small(
    int d, const int* __restrict__ left, const int* __restrict__ right,
    const float4* __restrict__ W4, const float* __restrict__ bW)
{
    int cnt = g_cnt[d];
    __shared__ float4 pair[256];   // 1024 floats = [h_l ; h_r]
    int tid = threadIdx.x;
    int lane = tid & 31, w = tid >> 5;
    int n0 = blockIdx.y << 7;      // 128 outputs per block
    float* Hf = (float*)g_H;

    for (int bx = blockIdx.x; bx < cnt; bx += gridDim.x) {
        int node = g_list[d][bx];
        int cl = left[node], cr = right[node];
        __syncthreads();
        pair[tid] = (tid < 128) ? g_H[cl * E4 + tid] : g_H[cr * E4 + tid - 128];
        __syncthreads();
#pragma unroll 1
        for (int o = 0; o < 16; o++) {
            int n = n0 + w * 16 + o;
            const float4* wrow = W4 + n * 256;
            float acc = 0.f;
#pragma unroll
            for (int it = 0; it < 8; it++) {
                float4 wv = wrow[lane + it * 32];
                float4 pv = pair[lane + it * 32];
                acc += wv.x * pv.x + wv.y * pv.y + wv.z * pv.z + wv.w * pv.w;
            }
#pragma unroll
            for (int off = 16; off; off >>= 1)
                acc += __shfl_xor_sync(0xffffffffu, acc, off);
            if (lane == 0)
                Hf[node * EMBED + n] = fmaxf(acc + bW[n], 0.f);
        }
    }
}

// ---------------- logits: out[i][c] = H[i] . P[c] + bP[c] ----------------
__global__ void k_logits(const float4* __restrict__ P4,
                         const float* __restrict__ bP,
                         float* __restrict__ out) {
    int gw = (blockIdx.x * blockDim.x + threadIdx.x) >> 5;
    int lane = threadIdx.x & 31;
    if (gw >= NNODES) return;
    float4 h[4];
#pragma unroll
    for (int i = 0; i < 4; i++) h[i] = g_H[gw * E4 + lane + i * 32];
#pragma unroll
    for (int c = 0; c < 5; c++) {
        float acc = 0.f;
#pragma unroll
        for (int i = 0; i < 4; i++) {
            float4 p = P4[c * E4 + lane + i * 32];
            acc += p.x * h[i].x + p.y * h[i].y + p.z * h[i].z + p.w * h[i].w;
        }
#pragma unroll
        for (int off = 16; off; off >>= 1)
            acc += __shfl_xor_sync(0xffffffffu, acc, off);
        if (lane == 0) out[gw * 5 + c] = acc + bP[c];
    }
}

// ---------------- launch ----------------
extern "C" void kernel_launch(void* const* d_in, const int* in_sizes, int n_in,
                              void* d_out, int out_size) {
    const int*   is_leaf = (const int*)d_in[0];
    const int*   word    = (const int*)d_in[1];
    const int*   left    = (const int*)d_in[2];
    const int*   right   = (const int*)d_in[3];
    const float* emb     = (const float*)d_in[4];
    const float* W       = (const float*)d_in[5];
    const float* bW      = (const float*)d_in[6];
    const float* P       = (const float*)d_in[7];
    const float* bP      = (const float*)d_in[8];
    float* out = (float*)d_out;

    k_zero<<<1, 32>>>();
    k_bucket<<<(NNODES + 255) / 256, 256>>>(is_leaf, left);
    k_leaf<<<(NNODES * 128 + 255) / 256, 256>>>(is_leaf, word, (const float4*)emb);

    for (int d = 1; d <= 13; d++) {
        int cnt = LEAVES >> d;   // expected level size (kernels read actual count)
        if (cnt >= 64) {
            int ZS = (d <= 3) ? 4 : 8;
            int mt = (cnt + 127) / 128; if (mt < 1) mt = 1;
            k_partial<<<dim3(mt, 4, ZS), 256>>>(d, ZS, left, right, (const float4*)W);
            int cb = (cnt * 128 + 255) / 256; if (cb < 1) cb = 1;
            k_combine<<<cb, 256>>>(d, ZS, (const float4*)bW);
        } else {
            int gx = cnt < 1 ? 1 : cnt;
            k_small<<<dim3(gx, 4), 256>>>(d, left, right, (const float4*)W, bW);
        }
    }

    k_logits<<<(NNODES * 32 + 255) / 256, 256>>>((const float4*)P, bP, out);
}